// round 8
// baseline (speedup 1.0000x reference)
#include <cuda_runtime.h>
#include <stdint.h>

#define B_  32
#define H_  512
#define W_  512
#define PIX_PER_IMG (H_ * W_)                 // 262144
#define CPB 128                               // moments chunks per batch (= shift blocks per batch)
#define GRID_TOTAL (B_ * CPB)                 // 4096 blocks
#define MF4 (PIX_PER_IMG / CPB / 4)           // 512 float4 of mk per block
#define SHIFT_ELEMS 8                         // 8 float4 pixels per thread

// Scratch (no allocations allowed) — zero-initialized, self-resetting.
__device__ float        g_part[GRID_TOTAL * 3];
__device__ int          g_shift[B_ * 2];      // (dx, dy) per batch
__device__ unsigned int g_cnt[B_];            // per-batch moments arrival counters
__device__ unsigned int g_ready[B_];          // per-batch "shift may start"
__device__ unsigned int g_done;               // global completion counter

// ---------------------------------------------------------------------------
// Single fused kernel, moments spread over ALL blocks.
// Phase 1: every block reduces its 8KB slice of mk (2 float4/thread, MLP=2
//   but 4096-block-wide so the read runs at full chip width); last arrival
//   per batch finalizes (dx,dy) deterministically and releases g_ready[b].
// Phase 2: spin on own batch's flag, then shifted copy of the same slice
//   position. Last finished block overall resets flags for graph replay.
// Deadlock-free: >=6 blocks/SM resident (888 >= 128 blocks per batch), CTAs
// issue in bid order, so the lowest unfinished batch always has all 128 of
// its blocks resident -> finalizes -> its spinners retire (induction).
// ---------------------------------------------------------------------------
__global__ __launch_bounds__(256, 6)
void fused_kernel(const float4* __restrict__ x,
                  const float*  __restrict__ mk,
                  float4* __restrict__ out)
{
    const int bid   = blockIdx.x;
    const int b     = bid >> 7;               // batch
    const int chunk = bid & (CPB - 1);        // 0..127
    const int t     = threadIdx.x;
    const int lane  = t & 31;
    const int wid   = t >> 5;

    // ======================= Phase 1: moments slice =======================
    {
        const float4* base =
            (const float4*)(mk + (size_t)b * PIX_PER_IMG) + chunk * MF4;

        const float4 v0 = base[t];
        const float4 v1 = base[t + 256];

        float s0 = 0.f, s1 = 0.f, s2 = 0.f;
#pragma unroll
        for (int i = 0; i < 2; i++) {
            const float4 v = (i == 0) ? v0 : v1;
            const int p = chunk * (MF4 * 4) + (t + i * 256) * 4;
            const int h = p >> 9;
            const int w = p & (W_ - 1);
            const float ry  = (float)(h - (H_ / 2));
            const float rx0 = (float)(w - (W_ / 2));
            const float sum = v.x + v.y + v.z + v.w;
            s0 += sum;
            s2 += ry * sum;
            s1 += rx0 * v.x + (rx0 + 1.f) * v.y + (rx0 + 2.f) * v.z
                + (rx0 + 3.f) * v.w;
        }

        // Warp butterfly reduce (deterministic fixed order)
#pragma unroll
        for (int m = 16; m > 0; m >>= 1) {
            s0 += __shfl_xor_sync(0xffffffffu, s0, m);
            s1 += __shfl_xor_sync(0xffffffffu, s1, m);
            s2 += __shfl_xor_sync(0xffffffffu, s2, m);
        }

        __shared__ float w0[8], w1[8], w2[8];
        if (lane == 0) { w0[wid] = s0; w1[wid] = s1; w2[wid] = s2; }
        __syncthreads();

        __shared__ bool isLast;
        if (t == 0) {
            float r0 = 0.f, r1 = 0.f, r2 = 0.f;
#pragma unroll
            for (int i = 0; i < 8; i++) { r0 += w0[i]; r1 += w1[i]; r2 += w2[i]; }
            const int o = bid * 3;
            g_part[o + 0] = r0;
            g_part[o + 1] = r1;
            g_part[o + 2] = r2;
            __threadfence();
            isLast = (atomicAdd(&g_cnt[b], 1u) == CPB - 1);
        }
        __syncthreads();

        if (isLast) {
            // Fixed-order tree over the 128 partials, independent of arrival.
            __shared__ float f0[CPB], f1[CPB], f2[CPB];
            if (t < CPB) {
                const int o = (b * CPB + t) * 3;
                f0[t] = g_part[o + 0];
                f1[t] = g_part[o + 1];
                f2[t] = g_part[o + 2];
            }
            __syncthreads();
#pragma unroll
            for (int st = CPB / 2; st > 0; st >>= 1) {
                if (t < st) {
                    f0[t] += f0[t + st];
                    f1[t] += f1[t + st];
                    f2[t] += f2[t + st];
                }
                __syncthreads();
            }
            if (t == 0) {
                const float m00 = fmaxf(0.001f, f0[0]);
                // rintf = round-half-even, matching jnp.round
                g_shift[b * 2 + 0] = (int)rintf(f1[0] / m00);   // dx
                g_shift[b * 2 + 1] = (int)rintf(f2[0] / m00);   // dy
                g_cnt[b] = 0u;                   // self-reset for next replay
                __threadfence();                 // release g_shift before flag
                atomicExch(&g_ready[b], 1u);     // open the gate for batch b
            }
        }
    }

    // ======================= Phase 2: shifted copy =======================
    if (t == 0) {
        while (atomicAdd(&g_ready[b], 0u) == 0u) __nanosleep(32);
    }
    __syncthreads();
    __threadfence();                              // acquire before reading g_shift

    const int dx = ((volatile int*)g_shift)[b * 2 + 0];
    const int dy = ((volatile int*)g_shift)[b * 2 + 1];

    const int base = chunk * (256 * SHIFT_ELEMS);
    const float4* xb = x + ((size_t)b << 18);
    float4* ob       = out + ((size_t)b << 18);

    float4 v[SHIFT_ELEMS];
#pragma unroll
    for (int k = 0; k < SHIFT_ELEMS; k++) {
        const int p = base + k * 256 + t;
        const int h = p >> 9;
        const int w = p & (W_ - 1);
        const int sh = h + dy;
        const int sw = w + dx;
        v[k] = make_float4(0.f, 0.f, 0.f, 0.f);
        if ((unsigned)sh < (unsigned)H_ && (unsigned)sw < (unsigned)W_)
            v[k] = xb[(sh << 9) + sw];
    }
#pragma unroll
    for (int k = 0; k < SHIFT_ELEMS; k++)
        ob[base + k * 256 + t] = v[k];

    // ---- Replay cleanup: last block overall resets the gates. By then every
    // block has passed its spin, so clearing g_ready cannot strand anyone.
    __syncthreads();
    if (t == 0) {
        if (atomicAdd(&g_done, 1u) == GRID_TOTAL - 1) {
#pragma unroll
            for (int i = 0; i < B_; i++) g_ready[i] = 0u;
            g_done = 0u;
            __threadfence();
        }
    }
}

// ---------------------------------------------------------------------------
extern "C" void kernel_launch(void* const* d_in, const int* in_sizes, int n_in,
                              void* d_out, int out_size)
{
    const float* x  = (const float*)d_in[0];   // [32,512,512,4]
    const float* mk = (const float*)d_in[1];   // [32,512,512,1]

    fused_kernel<<<GRID_TOTAL, 256>>>((const float4*)x, mk, (float4*)d_out);
}

// round 9
// speedup vs baseline: 1.6214x; 1.6214x over previous
#include <cuda_runtime.h>
#include <stdint.h>

#define B_  32
#define H_  512
#define W_  512
#define PIX_PER_IMG (H_ * W_)                    // 262144
#define CHUNKS 64                                // moments blocks per batch
#define F4_PER_CHUNK (PIX_PER_IMG / CHUNKS / 4)  // 1024 float4 per block
#define F4_PER_THREAD (F4_PER_CHUNK / 256)       // 4 (front-batched, MLP_p1=4)

// Scratch (no allocations allowed)
__device__ float        g_part[B_ * CHUNKS * 3];
__device__ int          g_shift[B_ * 2];         // (dx, dy) per batch
__device__ unsigned int g_cnt[B_];               // zero-init; self-reset each launch

// ---------------------------------------------------------------------------
// Stage 1 (fused): per-chunk partial moments of mk + last-block finalize.
// 2048 blocks x 16KB: chip-width read. Deterministic: fixed accumulation
// order, butterfly shuffle reduce, fixed-order finalize tree.
// ---------------------------------------------------------------------------
__global__ __launch_bounds__(256) void moments_fused(const float* __restrict__ mk)
{
    const int b     = blockIdx.y;
    const int chunk = blockIdx.x;       // 0..63
    const int t     = threadIdx.x;      // 0..255
    const int lane  = t & 31;
    const int wid   = t >> 5;           // 0..7

    const float4* base =
        (const float4*)(mk + (size_t)b * PIX_PER_IMG) + chunk * F4_PER_CHUNK;

    // Front-batch all 4 independent loads (MLP_p1=4).
    float4 v[F4_PER_THREAD];
#pragma unroll
    for (int i = 0; i < F4_PER_THREAD; i++)
        v[i] = base[t + i * 256];

    float s0 = 0.f, s1 = 0.f, s2 = 0.f;
#pragma unroll
    for (int i = 0; i < F4_PER_THREAD; i++) {
        const int p = chunk * (F4_PER_CHUNK * 4) + (t + i * 256) * 4;
        const int h = p >> 9;
        const int w = p & (W_ - 1);
        const float ry  = (float)(h - (H_ / 2));
        const float rx0 = (float)(w - (W_ / 2));
        const float sum = v[i].x + v[i].y + v[i].z + v[i].w;
        s0 += sum;
        s2 += ry * sum;
        s1 += rx0 * v[i].x + (rx0 + 1.f) * v[i].y + (rx0 + 2.f) * v[i].z
            + (rx0 + 3.f) * v[i].w;
    }

    // Warp butterfly reduce (deterministic fixed order)
#pragma unroll
    for (int m = 16; m > 0; m >>= 1) {
        s0 += __shfl_xor_sync(0xffffffffu, s0, m);
        s1 += __shfl_xor_sync(0xffffffffu, s1, m);
        s2 += __shfl_xor_sync(0xffffffffu, s2, m);
    }

    __shared__ float w0[8], w1[8], w2[8];
    if (lane == 0) { w0[wid] = s0; w1[wid] = s1; w2[wid] = s2; }
    __syncthreads();

    __shared__ bool isLast;
    if (t == 0) {
        float r0 = 0.f, r1 = 0.f, r2 = 0.f;
#pragma unroll
        for (int i = 0; i < 8; i++) { r0 += w0[i]; r1 += w1[i]; r2 += w2[i]; }
        const int o = (b * CHUNKS + chunk) * 3;
        g_part[o + 0] = r0;
        g_part[o + 1] = r1;
        g_part[o + 2] = r2;
        __threadfence();
        isLast = (atomicAdd(&g_cnt[b], 1u) == CHUNKS - 1);
    }
    __syncthreads();

    if (isLast) {
        __shared__ float f0[CHUNKS], f1[CHUNKS], f2[CHUNKS];
        if (t < CHUNKS) {
            const int o = (b * CHUNKS + t) * 3;
            f0[t] = g_part[o + 0];
            f1[t] = g_part[o + 1];
            f2[t] = g_part[o + 2];
        }
        __syncthreads();
#pragma unroll
        for (int st = CHUNKS / 2; st > 0; st >>= 1) {
            if (t < st) {
                f0[t] += f0[t + st];
                f1[t] += f1[t + st];
                f2[t] += f2[t + st];
            }
            __syncthreads();
        }
        if (t == 0) {
            const float m00 = fmaxf(0.001f, f0[0]);
            // rintf = round-half-even, matching jnp.round
            g_shift[b * 2 + 0] = (int)rintf(f1[0] / m00);   // dx
            g_shift[b * 2 + 1] = (int)rintf(f2[0] / m00);   // dy
            g_cnt[b] = 0u;      // self-reset -> state-clean for next replay
            __threadfence();
        }
    }
}

// ---------------------------------------------------------------------------
// Stage 2: shifted copy (exact R3 version — best measured: 37.4us).
// 8 pixels (8x float4) per thread; independent loads front-batched (MLP=8).
// out[b,h,w] = x[b, h+dy, w+dx] if in-bounds else 0   (clamped-pad semantics)
// ---------------------------------------------------------------------------
#define SHIFT_ELEMS 8
__global__ __launch_bounds__(256) void shift_kernel(const float4* __restrict__ x,
                                                    float4* __restrict__ out)
{
    const int b    = blockIdx.y;
    const int base = blockIdx.x * (256 * SHIFT_ELEMS);   // pixel base in image
    const int t    = threadIdx.x;

    const int dx = g_shift[b * 2 + 0];
    const int dy = g_shift[b * 2 + 1];

    const float4* xb = x + ((size_t)b << 18);
    float4* ob       = out + ((size_t)b << 18);

    float4 v[SHIFT_ELEMS];
#pragma unroll
    for (int k = 0; k < SHIFT_ELEMS; k++) {
        const int p = base + k * 256 + t;
        const int h = p >> 9;
        const int w = p & (W_ - 1);
        const int sh = h + dy;
        const int sw = w + dx;
        v[k] = make_float4(0.f, 0.f, 0.f, 0.f);
        if ((unsigned)sh < (unsigned)H_ && (unsigned)sw < (unsigned)W_)
            v[k] = xb[(sh << 9) + sw];
    }
#pragma unroll
    for (int k = 0; k < SHIFT_ELEMS; k++)
        ob[base + k * 256 + t] = v[k];
}

// ---------------------------------------------------------------------------
extern "C" void kernel_launch(void* const* d_in, const int* in_sizes, int n_in,
                              void* d_out, int out_size)
{
    const float* x  = (const float*)d_in[0];   // [32,512,512,4]
    const float* mk = (const float*)d_in[1];   // [32,512,512,1]

    dim3 g1(CHUNKS, B_);                       // (64, 32) = 2048 blocks
    moments_fused<<<g1, 256>>>(mk);

    dim3 g2(PIX_PER_IMG / (256 * SHIFT_ELEMS), B_);   // (128, 32)
    shift_kernel<<<g2, 256>>>((const float4*)x, (float4*)d_out);
}

// round 10
// speedup vs baseline: 1.6224x; 1.0006x over previous
#include <cuda_runtime.h>
#include <stdint.h>

#define B_  32
#define H_  512
#define W_  512
#define PIX_PER_IMG (H_ * W_)                    // 262144
#define CHUNKS 64                                // moments blocks per batch
#define F4_PER_CHUNK (PIX_PER_IMG / CHUNKS / 4)  // 1024 float4 per block
#define F4_PER_THREAD (F4_PER_CHUNK / 256)       // 4 (front-batched, MLP_p1=4)

// Scratch (no allocations allowed)
__device__ float        g_part[B_ * CHUNKS * 3];
__device__ int          g_shift[B_ * 2];         // (dx, dy) per batch
__device__ unsigned int g_cnt[B_];               // zero-init; self-reset each launch

// ---------------------------------------------------------------------------
// Stage 1 (fused): per-chunk partial moments of mk + last-block finalize.
// 2048 blocks x 16KB: chip-width read. Deterministic: fixed accumulation
// order, butterfly shuffle reduce, fixed-order finalize tree.
// Each block triggers the programmatic launch of the dependent shift kernel
// as soon as its partial is committed; griddepsync in the consumer provides
// the full-visibility guarantee, so trigger placement is correctness-neutral.
// ---------------------------------------------------------------------------
__global__ __launch_bounds__(256) void moments_fused(const float* __restrict__ mk)
{
    const int b     = blockIdx.y;
    const int chunk = blockIdx.x;       // 0..63
    const int t     = threadIdx.x;      // 0..255
    const int lane  = t & 31;
    const int wid   = t >> 5;           // 0..7

    const float4* base =
        (const float4*)(mk + (size_t)b * PIX_PER_IMG) + chunk * F4_PER_CHUNK;

    // Front-batch all 4 independent loads (MLP_p1=4).
    float4 v[F4_PER_THREAD];
#pragma unroll
    for (int i = 0; i < F4_PER_THREAD; i++)
        v[i] = base[t + i * 256];

    float s0 = 0.f, s1 = 0.f, s2 = 0.f;
#pragma unroll
    for (int i = 0; i < F4_PER_THREAD; i++) {
        const int p = chunk * (F4_PER_CHUNK * 4) + (t + i * 256) * 4;
        const int h = p >> 9;
        const int w = p & (W_ - 1);
        const float ry  = (float)(h - (H_ / 2));
        const float rx0 = (float)(w - (W_ / 2));
        const float sum = v[i].x + v[i].y + v[i].z + v[i].w;
        s0 += sum;
        s2 += ry * sum;
        s1 += rx0 * v[i].x + (rx0 + 1.f) * v[i].y + (rx0 + 2.f) * v[i].z
            + (rx0 + 3.f) * v[i].w;
    }

    // Warp butterfly reduce (deterministic fixed order)
#pragma unroll
    for (int m = 16; m > 0; m >>= 1) {
        s0 += __shfl_xor_sync(0xffffffffu, s0, m);
        s1 += __shfl_xor_sync(0xffffffffu, s1, m);
        s2 += __shfl_xor_sync(0xffffffffu, s2, m);
    }

    __shared__ float w0[8], w1[8], w2[8];
    if (lane == 0) { w0[wid] = s0; w1[wid] = s1; w2[wid] = s2; }
    __syncthreads();

    __shared__ bool isLast;
    if (t == 0) {
        float r0 = 0.f, r1 = 0.f, r2 = 0.f;
#pragma unroll
        for (int i = 0; i < 8; i++) { r0 += w0[i]; r1 += w1[i]; r2 += w2[i]; }
        const int o = (b * CHUNKS + chunk) * 3;
        g_part[o + 0] = r0;
        g_part[o + 1] = r1;
        g_part[o + 2] = r2;
        __threadfence();
        isLast = (atomicAdd(&g_cnt[b], 1u) == CHUNKS - 1);
        // Allow the dependent shift grid to start staging now.
        cudaTriggerProgrammaticLaunchCompletion();
    }
    __syncthreads();

    if (isLast) {
        __shared__ float f0[CHUNKS], f1[CHUNKS], f2[CHUNKS];
        if (t < CHUNKS) {
            const int o = (b * CHUNKS + t) * 3;
            f0[t] = g_part[o + 0];
            f1[t] = g_part[o + 1];
            f2[t] = g_part[o + 2];
        }
        __syncthreads();
#pragma unroll
        for (int st = CHUNKS / 2; st > 0; st >>= 1) {
            if (t < st) {
                f0[t] += f0[t + st];
                f1[t] += f1[t + st];
                f2[t] += f2[t + st];
            }
            __syncthreads();
        }
        if (t == 0) {
            const float m00 = fmaxf(0.001f, f0[0]);
            // rintf = round-half-even, matching jnp.round
            g_shift[b * 2 + 0] = (int)rintf(f1[0] / m00);   // dx
            g_shift[b * 2 + 1] = (int)rintf(f2[0] / m00);   // dy
            g_cnt[b] = 0u;      // self-reset -> state-clean for next replay
            __threadfence();
        }
    }
}

// ---------------------------------------------------------------------------
// Stage 2: shifted copy (R3/R8 best config: 8x float4/thread, MLP=8).
// PDL consumer: griddepsync before reading g_shift guarantees the moments
// grid's writes (including g_shift) are complete and visible.
// out[b,h,w] = x[b, h+dy, w+dx] if in-bounds else 0   (clamped-pad semantics)
// ---------------------------------------------------------------------------
#define SHIFT_ELEMS 8
__global__ __launch_bounds__(256) void shift_kernel(const float4* __restrict__ x,
                                                    float4* __restrict__ out)
{
    const int b    = blockIdx.y;
    const int base = blockIdx.x * (256 * SHIFT_ELEMS);   // pixel base in image
    const int t    = threadIdx.x;

    const float4* xb = x + ((size_t)b << 18);
    float4* ob       = out + ((size_t)b << 18);

    // Wait for the moments grid to complete (overlaps our launch/stage-in).
    cudaGridDependencySynchronize();

    const int dx = g_shift[b * 2 + 0];
    const int dy = g_shift[b * 2 + 1];

    float4 v[SHIFT_ELEMS];
#pragma unroll
    for (int k = 0; k < SHIFT_ELEMS; k++) {
        const int p = base + k * 256 + t;
        const int h = p >> 9;
        const int w = p & (W_ - 1);
        const int sh = h + dy;
        const int sw = w + dx;
        v[k] = make_float4(0.f, 0.f, 0.f, 0.f);
        if ((unsigned)sh < (unsigned)H_ && (unsigned)sw < (unsigned)W_)
            v[k] = xb[(sh << 9) + sw];
    }
#pragma unroll
    for (int k = 0; k < SHIFT_ELEMS; k++)
        ob[base + k * 256 + t] = v[k];
}

// ---------------------------------------------------------------------------
extern "C" void kernel_launch(void* const* d_in, const int* in_sizes, int n_in,
                              void* d_out, int out_size)
{
    const float* x  = (const float*)d_in[0];   // [32,512,512,4]
    const float* mk = (const float*)d_in[1];   // [32,512,512,1]

    dim3 g1(CHUNKS, B_);                       // (64, 32) = 2048 blocks
    moments_fused<<<g1, 256>>>(mk);

    // Dependent launch with programmatic stream serialization (PDL).
    cudaLaunchConfig_t cfg = {};
    cfg.gridDim  = dim3(PIX_PER_IMG / (256 * SHIFT_ELEMS), B_);   // (128, 32)
    cfg.blockDim = dim3(256);
    cudaLaunchAttribute attrs[1];
    attrs[0].id = cudaLaunchAttributeProgrammaticStreamSerialization;
    attrs[0].val.programmaticStreamSerializationAllowed = 1;
    cfg.attrs = attrs;
    cfg.numAttrs = 1;
    cudaLaunchKernelEx(&cfg, shift_kernel, (const float4*)x, (float4*)d_out);
}